// round 6
// baseline (speedup 1.0000x reference)
#include <cuda_runtime.h>
#include <math.h>
#include <stdint.h>

// Problem constants
#define NB      2
#define SEQ     2048
#define HDIM    2048
#define NHEADS  16
#define KVHEADS 4
#define HEADD   128
#define KVDIM   (KVHEADS * HEADD)   // 512
#define MROWS   (NB * SEQ)          // 4096
#define QSTRIDE (NHEADS * HEADD)    // 2048
#define KSTRIDE (KVHEADS * HEADD)   // 512

// Scratch (static device arrays; no runtime allocation allowed)
__device__ float g_Q[(size_t)MROWS * HDIM];   // (b,s,h,d) packed: ((b*S+s)*nh+h)*hd+d
__device__ float g_K[(size_t)MROWS * KVDIM];
__device__ float g_V[(size_t)MROWS * KVDIM];
__device__ float g_O[(size_t)MROWS * HDIM];

// ---------------------------------------------------------------------------
// SGEMM: C[M,N] = A[M,K] @ W[N,K]^T + bias[N]   (row-major, fp32)
// 128x128 block tile, K-step 8, 256 threads, 8x8 per thread.
// ---------------------------------------------------------------------------
__global__ void __launch_bounds__(256) sgemm_nt(
    const float* __restrict__ A, const float* __restrict__ W,
    const float* __restrict__ bias, float* __restrict__ C,
    int K, int N)
{
    __shared__ float As[8][128];   // As[k][m]
    __shared__ float Bs[8][128];   // Bs[k][n]

    const int tid = threadIdx.x;
    const int tx  = tid & 15;
    const int ty  = tid >> 4;
    const int m0  = blockIdx.y * 128;
    const int n0  = blockIdx.x * 128;

    const int r  = tid >> 1;        // 0..127
    const int s4 = (tid & 1) * 4;   // 0 or 4

    const float* Ap = A + (size_t)(m0 + r) * K + s4;
    const float* Wp = W + (size_t)(n0 + r) * K + s4;

    float acc[8][8];
    #pragma unroll
    for (int i = 0; i < 8; i++)
        #pragma unroll
        for (int j = 0; j < 8; j++) acc[i][j] = 0.0f;

    for (int kt = 0; kt < K; kt += 8) {
        float4 av = *(const float4*)(Ap + kt);
        float4 wv = *(const float4*)(Wp + kt);
        __syncthreads();   // previous tile fully consumed
        As[s4 + 0][r] = av.x; As[s4 + 1][r] = av.y;
        As[s4 + 2][r] = av.z; As[s4 + 3][r] = av.w;
        Bs[s4 + 0][r] = wv.x; Bs[s4 + 1][r] = wv.y;
        Bs[s4 + 2][r] = wv.z; Bs[s4 + 3][r] = wv.w;
        __syncthreads();

        #pragma unroll
        for (int k = 0; k < 8; k++) {
            float4 a0 = *(const float4*)&As[k][ty * 4];
            float4 a1 = *(const float4*)&As[k][64 + ty * 4];
            float4 b0 = *(const float4*)&Bs[k][tx * 4];
            float4 b1 = *(const float4*)&Bs[k][64 + tx * 4];
            float a[8] = {a0.x, a0.y, a0.z, a0.w, a1.x, a1.y, a1.z, a1.w};
            float b[8] = {b0.x, b0.y, b0.z, b0.w, b1.x, b1.y, b1.z, b1.w};
            #pragma unroll
            for (int i = 0; i < 8; i++)
                #pragma unroll
                for (int j = 0; j < 8; j++)
                    acc[i][j] += a[i] * b[j];
        }
    }

    // Epilogue with fused bias
    #pragma unroll
    for (int i = 0; i < 8; i++) {
        int row = (i < 4) ? (ty * 4 + i) : (64 + ty * 4 + (i - 4));
        float* Crow = C + (size_t)(m0 + row) * N + n0;
        #pragma unroll
        for (int jh = 0; jh < 2; jh++) {
            int c = jh * 64 + tx * 4;
            float4 o;
            o.x = acc[i][jh * 4 + 0] + bias[n0 + c + 0];
            o.y = acc[i][jh * 4 + 1] + bias[n0 + c + 1];
            o.z = acc[i][jh * 4 + 2] + bias[n0 + c + 2];
            o.w = acc[i][jh * 4 + 3] + bias[n0 + c + 3];
            *(float4*)(Crow + c) = o;
        }
    }
}

// ---------------------------------------------------------------------------
// RoPE in-place on a (B,S,heads,128) tensor. One thread per (b,s,h,d<64) pair.
// out[d]    = x[d]*cos[s,d]   - x[d+64]*sin[s,d]
// out[d+64] = x[d+64]*cos[s,d] + x[d]*sin[s,d]     (cos/sin halves identical)
// ---------------------------------------------------------------------------
__global__ void rope_kernel(float* __restrict__ T,
                            const float* __restrict__ cosb,
                            const float* __restrict__ sinb,
                            int heads, int total)
{
    int idx = blockIdx.x * blockDim.x + threadIdx.x;
    if (idx >= total) return;
    int d  = idx & 63;
    int h  = (idx >> 6) % heads;
    int bs = idx / (64 * heads);
    int s  = bs % SEQ;
    float c  = cosb[s * HEADD + d];
    float sn = sinb[s * HEADD + d];
    float* p = T + ((size_t)bs * heads + h) * HEADD;
    float q0 = p[d], q1 = p[d + 64];
    p[d]      = q0 * c - q1 * sn;
    p[d + 64] = q1 * c + q0 * sn;
}

// ---------------------------------------------------------------------------
// Flash attention, causal, GQA (rep=4). BQ=BK=64, hd=128, 256 threads.
// Q and K stored d-major (transposed) in smem; V natural; P staged in smem.
// smem: Qst[128][64] + Kst[128][64] + Vs[64][128] + Ps[64][64] = 112 KB
// ---------------------------------------------------------------------------
#define BQ 64
#define BK 64
#define ATTN_SMEM ((2 * 128 * 64 + 64 * 128 + 64 * 64) * 4)  // 114688 bytes

__global__ void __launch_bounds__(256) attn_kernel()
{
    extern __shared__ float sm[];
    float (*Qst)[64]  = (float(*)[64]) sm;                          // [128][64]
    float (*Kst)[64]  = (float(*)[64])(sm + 128 * 64);              // [128][64]
    float (*Vs)[128]  = (float(*)[128])(sm + 2 * 128 * 64);         // [64][128]
    float (*Ps)[64]   = (float(*)[64]) (sm + 2 * 128 * 64 + 64 * 128); // [64][64]

    const int tid = threadIdx.x;
    const int tx  = tid & 15;
    const int ty  = tid >> 4;

    // heavier (large q0) blocks first
    const int q0 = (gridDim.x - 1 - blockIdx.x) * BQ;
    const int bh = blockIdx.y;
    const int b  = bh / NHEADS;
    const int h  = bh % NHEADS;
    const int kh = h / (NHEADS / KVHEADS);

    const float* Qbase = g_Q + ((size_t)b * SEQ * NHEADS  + h)  * HEADD;
    const float* Kbase = g_K + ((size_t)b * SEQ * KVHEADS + kh) * HEADD;
    const float* Vbase = g_V + ((size_t)b * SEQ * KVHEADS + kh) * HEADD;

    const float SCALE = 0.08838834764831845f;  // 1/sqrt(128)

    // ---- load Q tile transposed (pre-scaled) ----
    #pragma unroll
    for (int it = 0; it < 2; it++) {
        int sb   = tid + it * 256;     // 0..511
        int rb   = sb & 15;            // row block
        int db   = sb >> 4;            // d block (0..31)
        int row0 = rb * 4, d0 = db * 4;
        float4 r0 = *(const float4*)(Qbase + (size_t)(q0 + row0 + 0) * QSTRIDE + d0);
        float4 r1 = *(const float4*)(Qbase + (size_t)(q0 + row0 + 1) * QSTRIDE + d0);
        float4 r2 = *(const float4*)(Qbase + (size_t)(q0 + row0 + 2) * QSTRIDE + d0);
        float4 r3 = *(const float4*)(Qbase + (size_t)(q0 + row0 + 3) * QSTRIDE + d0);
        float4 c;
        c.x = r0.x * SCALE; c.y = r1.x * SCALE; c.z = r2.x * SCALE; c.w = r3.x * SCALE;
        *(float4*)&Qst[d0 + 0][row0] = c;
        c.x = r0.y * SCALE; c.y = r1.y * SCALE; c.z = r2.y * SCALE; c.w = r3.y * SCALE;
        *(float4*)&Qst[d0 + 1][row0] = c;
        c.x = r0.z * SCALE; c.y = r1.z * SCALE; c.z = r2.z * SCALE; c.w = r3.z * SCALE;
        *(float4*)&Qst[d0 + 2][row0] = c;
        c.x = r0.w * SCALE; c.y = r1.w * SCALE; c.z = r2.w * SCALE; c.w = r3.w * SCALE;
        *(float4*)&Qst[d0 + 3][row0] = c;
    }

    float m_i[4], l_i[4];
    float4 o_acc[4][2];
    #pragma unroll
    for (int i = 0; i < 4; i++) {
        m_i[i] = -INFINITY;
        l_i[i] = 0.0f;
        o_acc[i][0] = make_float4(0.f, 0.f, 0.f, 0.f);
        o_acc[i][1] = make_float4(0.f, 0.f, 0.f, 0.f);
    }

    const int ktiles = q0 / BK + 1;
    for (int kt = 0; kt < ktiles; kt++) {
        const int kv0 = kt * BK;
        __syncthreads();   // previous iteration's Ps/Vs reads complete

        // ---- load K tile transposed ----
        #pragma unroll
        for (int it = 0; it < 2; it++) {
            int sb   = tid + it * 256;
            int rb   = sb & 15;
            int db   = sb >> 4;
            int row0 = rb * 4, d0 = db * 4;
            float4 r0 = *(const float4*)(Kbase + (size_t)(kv0 + row0 + 0) * KSTRIDE + d0);
            float4 r1 = *(const float4*)(Kbase + (size_t)(kv0 + row0 + 1) * KSTRIDE + d0);
            float4 r2 = *(const float4*)(Kbase + (size_t)(kv0 + row0 + 2) * KSTRIDE + d0);
            float4 r3 = *(const float4*)(Kbase + (size_t)(kv0 + row0 + 3) * KSTRIDE + d0);
            float4 c;
            c.x = r0.x; c.y = r1.x; c.z = r2.x; c.w = r3.x; *(float4*)&Kst[d0 + 0][row0] = c;
            c.x = r0.y; c.y = r1.y; c.z = r2.y; c.w = r3.y; *(float4*)&Kst[d0 + 1][row0] = c;
            c.x = r0.z; c.y = r1.z; c.z = r2.z; c.w = r3.z; *(float4*)&Kst[d0 + 2][row0] = c;
            c.x = r0.w; c.y = r1.w; c.z = r2.w; c.w = r3.w; *(float4*)&Kst[d0 + 3][row0] = c;
        }
        // ---- load V tile (natural layout, fully coalesced) ----
        #pragma unroll
        for (int it = 0; it < 8; it++) {
            int lin4 = it * 256 + tid;        // float4 index, 0..2047
            int row  = lin4 >> 5;
            int d4   = (lin4 & 31) * 4;
            *(float4*)&Vs[row][d4] =
                *(const float4*)(Vbase + (size_t)(kv0 + row) * KSTRIDE + d4);
        }
        __syncthreads();

        // ---- S = Q K^T (64x64, each thread 4x4) ----
        float sc[4][4];
        #pragma unroll
        for (int i = 0; i < 4; i++)
            #pragma unroll
            for (int j = 0; j < 4; j++) sc[i][j] = 0.0f;

        #pragma unroll 4
        for (int d = 0; d < 128; d++) {
            float4 qa = *(const float4*)&Qst[d][ty * 4];
            float4 kb = *(const float4*)&Kst[d][tx * 4];
            float a[4] = {qa.x, qa.y, qa.z, qa.w};
            float bb[4] = {kb.x, kb.y, kb.z, kb.w};
            #pragma unroll
            for (int i = 0; i < 4; i++)
                #pragma unroll
                for (int j = 0; j < 4; j++)
                    sc[i][j] += a[i] * bb[j];
        }

        // ---- causal mask (diagonal tile only) ----
        if (kv0 == q0) {
            #pragma unroll
            for (int i = 0; i < 4; i++)
                #pragma unroll
                for (int j = 0; j < 4; j++)
                    if (tx * 4 + j > ty * 4 + i) sc[i][j] = -1.0e30f;
        }

        // ---- online softmax per row (reduce across 16 lanes of same ty) ----
        #pragma unroll
        for (int i = 0; i < 4; i++) {
            float mx = fmaxf(fmaxf(sc[i][0], sc[i][1]), fmaxf(sc[i][2], sc[i][3]));
            #pragma unroll
            for (int w = 8; w >= 1; w >>= 1)
                mx = fmaxf(mx, __shfl_xor_sync(0xffffffffu, mx, w));
            float m_new = fmaxf(m_i[i], mx);
            float corr  = __expf(m_i[i] - m_new);
            float sum = 0.0f;
            #pragma unroll
            for (int j = 0; j < 4; j++) {
                float p = __expf(sc[i][j] - m_new);
                sc[i][j] = p;
                sum += p;
            }
            #pragma unroll
            for (int w = 8; w >= 1; w >>= 1)
                sum += __shfl_xor_sync(0xffffffffu, sum, w);
            l_i[i] = l_i[i] * corr + sum;
            m_i[i] = m_new;
            o_acc[i][0].x *= corr; o_acc[i][0].y *= corr;
            o_acc[i][0].z *= corr; o_acc[i][0].w *= corr;
            o_acc[i][1].x *= corr; o_acc[i][1].y *= corr;
            o_acc[i][1].z *= corr; o_acc[i][1].w *= corr;
            float4 pv = make_float4(sc[i][0], sc[i][1], sc[i][2], sc[i][3]);
            *(float4*)&Ps[ty * 4 + i][tx * 4] = pv;
        }
        __syncthreads();

        // ---- O += P V (each thread 4 rows x 8 cols) ----
        #pragma unroll 4
        for (int k = 0; k < BK; k++) {
            float4 v0 = *(const float4*)&Vs[k][tx * 4];
            float4 v1 = *(const float4*)&Vs[k][64 + tx * 4];
            #pragma unroll
            for (int i = 0; i < 4; i++) {
                float p = Ps[ty * 4 + i][k];
                o_acc[i][0].x += p * v0.x; o_acc[i][0].y += p * v0.y;
                o_acc[i][0].z += p * v0.z; o_acc[i][0].w += p * v0.w;
                o_acc[i][1].x += p * v1.x; o_acc[i][1].y += p * v1.y;
                o_acc[i][1].z += p * v1.z; o_acc[i][1].w += p * v1.w;
            }
        }
    }

    // ---- epilogue: normalize and write to g_O ----
    #pragma unroll
    for (int i = 0; i < 4; i++) {
        float inv = 1.0f / l_i[i];
        int s = q0 + ty * 4 + i;
        float* Orow = g_O + ((size_t)(b * SEQ + s) * NHEADS + h) * HEADD;
        float4 o0 = o_acc[i][0], o1 = o_acc[i][1];
        o0.x *= inv; o0.y *= inv; o0.z *= inv; o0.w *= inv;
        o1.x *= inv; o1.y *= inv; o1.z *= inv; o1.w *= inv;
        *(float4*)(Orow + tx * 4)      = o0;
        *(float4*)(Orow + 64 + tx * 4) = o1;
    }
}

// ---------------------------------------------------------------------------
extern "C" void kernel_launch(void* const* d_in, const int* in_sizes, int n_in,
                              void* d_out, int out_size)
{
    const float* x    = (const float*)d_in[0];
    const float* wq   = (const float*)d_in[1];
    const float* bq   = (const float*)d_in[2];
    const float* wk   = (const float*)d_in[3];
    const float* bk   = (const float*)d_in[4];
    const float* wv   = (const float*)d_in[5];
    const float* bv   = (const float*)d_in[6];
    const float* wo   = (const float*)d_in[7];
    const float* bo   = (const float*)d_in[8];
    const float* cosb = (const float*)d_in[9];
    const float* sinb = (const float*)d_in[10];
    float* out = (float*)d_out;

    float *Qp, *Kp, *Vp, *Op;
    cudaGetSymbolAddress((void**)&Qp, g_Q);
    cudaGetSymbolAddress((void**)&Kp, g_K);
    cudaGetSymbolAddress((void**)&Vp, g_V);
    cudaGetSymbolAddress((void**)&Op, g_O);

    cudaFuncSetAttribute(attn_kernel,
                         cudaFuncAttributeMaxDynamicSharedMemorySize, ATTN_SMEM);

    // 1-3. QKV projections (+bias)
    sgemm_nt<<<dim3(HDIM / 128,  MROWS / 128), 256>>>(x, wq, bq, Qp, HDIM, HDIM);
    sgemm_nt<<<dim3(KVDIM / 128, MROWS / 128), 256>>>(x, wk, bk, Kp, HDIM, KVDIM);
    sgemm_nt<<<dim3(KVDIM / 128, MROWS / 128), 256>>>(x, wv, bv, Vp, HDIM, KVDIM);

    // 4-5. RoPE on Q and K
    {
        int totq = NB * SEQ * NHEADS * 64;
        rope_kernel<<<(totq + 255) / 256, 256>>>(Qp, cosb, sinb, NHEADS, totq);
        int totk = NB * SEQ * KVHEADS * 64;
        rope_kernel<<<(totk + 255) / 256, 256>>>(Kp, cosb, sinb, KVHEADS, totk);
    }

    // 6. Causal GQA flash attention
    attn_kernel<<<dim3(SEQ / BQ, NB * NHEADS), 256, ATTN_SMEM>>>();

    // 7. Output projection (+bias) straight into d_out
    sgemm_nt<<<dim3(HDIM / 128, MROWS / 128), 256>>>(Op, wo, bo, out, HDIM, HDIM);
}